// round 10
// baseline (speedup 1.0000x reference)
#include <cuda_runtime.h>
#include <cstdint>

// ---------------------------------------------------------------------------
// Problem constants
// ---------------------------------------------------------------------------
#define N_NODES 50000
#define N_EDGES 400000
#define F_IN    256
#define HID     64
#define N_CLS   32
#define HEADS   8

// ---------------------------------------------------------------------------
// Static scratch. xl/xr plain row-major [node][h*c] (R7 fused-gat layout).
// *_s arrays are pre-split tf32 (hi,lo) float2 pairs.
// ---------------------------------------------------------------------------
__device__ float  g_xl1[N_NODES * HEADS * HID];    // 102.4 MB
__device__ float  g_xr1[N_NODES * HEADS * HID];    // 102.4 MB
__device__ float  g_h1 [N_NODES * HID];            // 12.8 MB
__device__ float  g_xl2[N_NODES * HEADS * N_CLS];  // 51.2 MB
__device__ float  g_xr2[N_NODES * HEADS * N_CLS];  // 51.2 MB
__device__ float2 g_xs  [N_NODES * F_IN];          // 102.4 MB split x
__device__ float2 g_h1s [N_NODES * HID];           // 25.6 MB  split h1
__device__ float2 g_wl1s[F_IN * HEADS * HID];
__device__ float2 g_wr1s[F_IN * HEADS * HID];
__device__ float2 g_wl2s[HID * HEADS * N_CLS];
__device__ float2 g_wr2s[HID * HEADS * N_CLS];
__device__ float2 g_wlins[F_IN * N_CLS];
__device__ int    g_deg   [N_NODES];
__device__ int    g_rowptr[N_NODES + 1];
__device__ int    g_cursor[N_NODES];
__device__ int    g_csr   [N_EDGES + N_NODES];
__device__ int    g_is64;

// ---------------------------------------------------------------------------
// tf32 helpers
// ---------------------------------------------------------------------------
__device__ __forceinline__ unsigned f2tf32(float x) {
    unsigned r;
    asm("cvt.rna.tf32.f32 %0, %1;" : "=r"(r) : "f"(x));
    return r;
}

// one-time hi/lo split: out[i] = (tf32(v), tf32(v - tf32(v)))
__global__ void k_split(const float* __restrict__ in, float2* __restrict__ out, int n) {
    int i = blockIdx.x * blockDim.x + threadIdx.x;
    if (i < n) {
        float v = in[i];
        unsigned h = f2tf32(v);
        float hf = __uint_as_float(h);
        out[i] = make_float2(hf, __uint_as_float(f2tf32(v - hf)));
    }
}

// ---------------------------------------------------------------------------
// edge_index dtype probe (int64 => all high words zero since ids < 2^31).
// ---------------------------------------------------------------------------
__global__ void k_flag_init() { g_is64 = 1; }

__global__ void k_detect(const int* __restrict__ p, int nPairs) {
    int i = blockIdx.x * blockDim.x + threadIdx.x;
    if (i < nPairs && p[2 * i + 1] != 0) g_is64 = 0;   // benign race: only writes 0
}

__device__ __forceinline__ int edge_at(const int* __restrict__ p, int e) {
    if (g_is64) return (int)(((const long long*)p)[e]);
    return p[e];
}

// ---------------------------------------------------------------------------
// CSR build (dst-major, self loops first, range-guarded)
// ---------------------------------------------------------------------------
__global__ void k_init_deg(int* __restrict__ deg, int n) {
    int i = blockIdx.x * blockDim.x + threadIdx.x;
    if (i < n) deg[i] = 1;
}

__global__ void k_hist(const int* __restrict__ ei, int E, int* __restrict__ deg) {
    int e = blockIdx.x * blockDim.x + threadIdx.x;
    if (e < E) {
        unsigned d = (unsigned)edge_at(ei, E + e);
        unsigned s = (unsigned)edge_at(ei, e);
        if (d < (unsigned)N_NODES && s < (unsigned)N_NODES)
            atomicAdd(&deg[d], 1);
    }
}

__global__ void k_scan(const int* __restrict__ deg, int* __restrict__ rowptr, int n) {
    __shared__ int sm[1024];
    __shared__ int s_carry;
    int t = threadIdx.x;
    if (t == 0) s_carry = 0;
    __syncthreads();
    for (int base = 0; base < n; base += 1024) {
        int i = base + t;
        int v = (i < n) ? deg[i] : 0;
        sm[t] = v;
        __syncthreads();
        #pragma unroll
        for (int off = 1; off < 1024; off <<= 1) {
            int add = (t >= off) ? sm[t - off] : 0;
            __syncthreads();
            sm[t] += add;
            __syncthreads();
        }
        int incl = sm[t];
        int carry = s_carry;
        if (i < n) rowptr[i] = carry + incl - v;
        __syncthreads();
        if (t == 1023) s_carry = carry + incl;
        __syncthreads();
    }
    if (t == 0) rowptr[n] = s_carry;
}

__global__ void k_cursor_self(const int* __restrict__ rowptr, int* __restrict__ cur,
                              int* __restrict__ csr, int n) {
    int i = blockIdx.x * blockDim.x + threadIdx.x;
    if (i < n) {
        int p = rowptr[i];
        csr[p] = i;
        cur[i] = p + 1;
    }
}

__global__ void k_scatter_edges(const int* __restrict__ ei, int E,
                                int* __restrict__ cur, int* __restrict__ csr) {
    int e = blockIdx.x * blockDim.x + threadIdx.x;
    if (e < E) {
        unsigned s = (unsigned)edge_at(ei, e);
        unsigned d = (unsigned)edge_at(ei, E + e);
        if (d < (unsigned)N_NODES && s < (unsigned)N_NODES)
            csr[atomicAdd(&cur[d], 1)] = (int)s;
    }
}

// ---------------------------------------------------------------------------
// Pure-MMA tf32 GEMM on PRE-SPLIT (hi,lo) float2 operands.
// C[M,N] = A[M,K] @ B[K,N] (+bias), fp32-accurate 3-term compensation.
// Block 128x64x8, 8 warps (4Mx2N), warp tile 32x32. cp.async double buffer.
// No cvt in the mainloop. K%8==0, N%4==0.
// ---------------------------------------------------------------------------
__device__ __forceinline__ void mma_tf32(float* c, const unsigned* a, const unsigned* b) {
    asm volatile(
        "mma.sync.aligned.m16n8k8.row.col.f32.tf32.tf32.f32 "
        "{%0,%1,%2,%3}, {%4,%5,%6,%7}, {%8,%9}, {%0,%1,%2,%3};"
        : "+f"(c[0]), "+f"(c[1]), "+f"(c[2]), "+f"(c[3])
        : "r"(a[0]), "r"(a[1]), "r"(a[2]), "r"(a[3]), "r"(b[0]), "r"(b[1]));
}

__device__ __forceinline__ void cp16(void* dst_smem, const void* src, bool pred) {
    unsigned saddr = (unsigned)__cvta_generic_to_shared(dst_smem);
    int sz = pred ? 16 : 0;
    asm volatile("cp.async.cg.shared.global [%0], [%1], 16, %2;"
                 :: "r"(saddr), "l"(src), "r"(sz));
}

__global__ void __launch_bounds__(256)
k_mma_s(const float2* __restrict__ A, const float2* __restrict__ B,
        float* __restrict__ C, int M, int N, int K,
        const float* __restrict__ bias) {
    constexpr int BM = 128, BN = 64, BK = 8;
    constexpr int BKP = 10, BNP = 66;           // float2 strides (pad)
    __shared__ alignas(16) float2 As2[2][BM][BKP];   // 20480 B
    __shared__ alignas(16) float2 Bs2[2][BK][BNP];   //  8448 B

    const int tid  = threadIdx.x;
    const int lane = tid & 31;
    const int wid  = tid >> 5;
    const int warpM = wid >> 1;
    const int warpN = wid & 1;
    const int gid = lane >> 2;
    const int tig = lane & 3;

    const int bm = blockIdx.y * BM;
    const int bn = blockIdx.x * BN;

    // A: 128x8 float2 per tile -> 2 cp16/thread
    const int aRow = tid >> 1;                 // 0..127
    const int aC   = (tid & 1) * 4;            // 0 or 4 (two cp16: +0,+2)
    const bool aOk = (bm + aRow) < M;
    // B: 8x64 float2 per tile -> 1 cp16/thread
    const int bRow = tid >> 5;                 // 0..7
    const int bC   = (tid & 31) * 2;           // 0..62
    const bool bOk = (bn + bC) < N;            // N%4==0, bC even => pair in-range together

    float acc[2][4][4];
    #pragma unroll
    for (int i = 0; i < 2; ++i)
        #pragma unroll
        for (int j = 0; j < 4; ++j)
            #pragma unroll
            for (int r = 0; r < 4; ++r) acc[i][j][r] = 0.f;

    const int nt = K / BK;
    const float2* aBase = A + (size_t)(bm + aRow) * K;

    cp16(&As2[0][aRow][aC],     aOk ? (const void*)(aBase + aC)     : (const void*)A, aOk);
    cp16(&As2[0][aRow][aC + 2], aOk ? (const void*)(aBase + aC + 2) : (const void*)A, aOk);
    cp16(&Bs2[0][bRow][bC],
         bOk ? (const void*)(B + (size_t)bRow * N + bn + bC) : (const void*)B, bOk);
    asm volatile("cp.async.commit_group;");
    asm volatile("cp.async.wait_group 0;" ::: "memory");
    __syncthreads();

    for (int t = 0; t < nt; ++t) {
        const int cur = t & 1;
        if (t + 1 < nt) {
            const int k0 = (t + 1) * BK;
            const int nxt = cur ^ 1;
            cp16(&As2[nxt][aRow][aC],     aOk ? (const void*)(aBase + k0 + aC)     : (const void*)A, aOk);
            cp16(&As2[nxt][aRow][aC + 2], aOk ? (const void*)(aBase + k0 + aC + 2) : (const void*)A, aOk);
            cp16(&Bs2[nxt][bRow][bC],
                 bOk ? (const void*)(B + (size_t)(k0 + bRow) * N + bn + bC) : (const void*)B, bOk);
            asm volatile("cp.async.commit_group;");
        }

        unsigned ahi[2][4], alo[2][4], bhi[4][2], blo[4][2];
        #pragma unroll
        for (int mf = 0; mf < 2; ++mf) {
            const int mb = warpM * 32 + mf * 16;
            float2 p0 = As2[cur][mb + gid    ][tig];
            float2 p1 = As2[cur][mb + gid + 8][tig];
            float2 p2 = As2[cur][mb + gid    ][tig + 4];
            float2 p3 = As2[cur][mb + gid + 8][tig + 4];
            ahi[mf][0] = __float_as_uint(p0.x); alo[mf][0] = __float_as_uint(p0.y);
            ahi[mf][1] = __float_as_uint(p1.x); alo[mf][1] = __float_as_uint(p1.y);
            ahi[mf][2] = __float_as_uint(p2.x); alo[mf][2] = __float_as_uint(p2.y);
            ahi[mf][3] = __float_as_uint(p3.x); alo[mf][3] = __float_as_uint(p3.y);
        }
        #pragma unroll
        for (int nf = 0; nf < 4; ++nf) {
            const int nb = warpN * 32 + nf * 8;
            float2 q0 = Bs2[cur][tig    ][nb + gid];
            float2 q1 = Bs2[cur][tig + 4][nb + gid];
            bhi[nf][0] = __float_as_uint(q0.x); blo[nf][0] = __float_as_uint(q0.y);
            bhi[nf][1] = __float_as_uint(q1.x); blo[nf][1] = __float_as_uint(q1.y);
        }

        #pragma unroll
        for (int mf = 0; mf < 2; ++mf)
            #pragma unroll
            for (int nf = 0; nf < 4; ++nf) {
                mma_tf32(acc[mf][nf], alo[mf], bhi[nf]);
                mma_tf32(acc[mf][nf], ahi[mf], blo[nf]);
                mma_tf32(acc[mf][nf], ahi[mf], bhi[nf]);
            }

        if (t + 1 < nt) {
            asm volatile("cp.async.wait_group 0;" ::: "memory");
            __syncthreads();
        }
    }

    #pragma unroll
    for (int mf = 0; mf < 2; ++mf) {
        #pragma unroll
        for (int nf = 0; nf < 4; ++nf) {
            const int col0 = bn + warpN * 32 + nf * 8 + 2 * tig;
            const int row0 = bm + warpM * 32 + mf * 16 + gid;
            #pragma unroll
            for (int half = 0; half < 2; ++half) {
                const int row = row0 + half * 8;
                if (row >= M) continue;
                #pragma unroll
                for (int c = 0; c < 2; ++c) {
                    const int col = col0 + c;
                    if (col < N) {
                        float v = acc[mf][nf][half * 2 + c];
                        if (bias) v += bias[col];
                        C[(size_t)row * N + col] = v;
                    }
                }
            }
        }
    }
}

// ---------------------------------------------------------------------------
// GATv2 edge+softmax+aggregate, fused per dst node (R7 known-best form).
// One block per dst node, 8 warps = 8 heads, lane = channel.
// ---------------------------------------------------------------------------
template <int C, bool RELU, bool ADD_RES>
__global__ void __launch_bounds__(256)
k_gatv2(const float* __restrict__ xl, const float* __restrict__ xr,
        const float* __restrict__ att, const float* __restrict__ bias,
        const int* __restrict__ rowptr, const int* __restrict__ csr,
        const float* __restrict__ resid, float* __restrict__ out) {
    constexpr int H = HEADS;
    constexpr int KC = C / 32;
    int node = blockIdx.x;
    int w = threadIdx.x >> 5;
    int l = threadIdx.x & 31;

    const float* xr_row = xr + (size_t)node * H * C + w * C;
    float xrv[KC], attv[KC], accv[KC];
    #pragma unroll
    for (int k = 0; k < KC; ++k) {
        xrv[k]  = xr_row[l + 32 * k];
        attv[k] = att[w * C + l + 32 * k];
        accv[k] = 0.f;
    }
    float denom = 0.f;

    int beg = rowptr[node], end = rowptr[node + 1];
    for (int idx = beg; idx < end; ++idx) {
        int s = csr[idx];
        const float* xl_row = xl + (size_t)s * H * C + w * C;
        float xlv[KC];
        float partial = 0.f;
        #pragma unroll
        for (int k = 0; k < KC; ++k) {
            xlv[k] = xl_row[l + 32 * k];
            float v = xlv[k] + xrv[k];
            v = (v > 0.f) ? v : 0.2f * v;      // leaky_relu(0.2)
            partial = fmaf(attv[k], v, partial);
        }
        #pragma unroll
        for (int off = 16; off > 0; off >>= 1)
            partial += __shfl_xor_sync(0xffffffffu, partial, off);
        float p = __expf(partial);
        denom += p;
        #pragma unroll
        for (int k = 0; k < KC; ++k)
            accv[k] = fmaf(p, xlv[k], accv[k]);
    }

    __shared__ float sh[H * C];
    float inv = 1.f / denom;
    #pragma unroll
    for (int k = 0; k < KC; ++k)
        sh[w * C + l + 32 * k] = accv[k] * inv;
    __syncthreads();

    if (threadIdx.x < C) {
        int c = threadIdx.x;
        float s = 0.f;
        #pragma unroll
        for (int h = 0; h < H; ++h) s += sh[h * C + c];
        s = s * (1.f / H) + bias[c];
        if (RELU) s = fmaxf(s, 0.f);
        if (ADD_RES) s += resid[(size_t)node * C + c];
        out[(size_t)node * C + c] = s;
    }
}

// ---------------------------------------------------------------------------
// Launch. First big GEMM at launch #4 (ncu's observed capture slot).
// ---------------------------------------------------------------------------
static inline int cdiv(int a, int b) { return (a + b - 1) / b; }

extern "C" void kernel_launch(void* const* d_in, const int* in_sizes, int n_in,
                              void* d_out, int out_size) {
    const float* x    = (const float*)d_in[0];
    const int*   ei   = (const int*)d_in[1];
    const float* Wl1  = (const float*)d_in[2];
    const float* Wr1  = (const float*)d_in[3];
    const float* att1 = (const float*)d_in[4];
    const float* b1   = (const float*)d_in[5];
    const float* Wl2  = (const float*)d_in[6];
    const float* Wr2  = (const float*)d_in[7];
    const float* att2 = (const float*)d_in[8];
    const float* b2   = (const float*)d_in[9];
    const float* Wlin = (const float*)d_in[10];
    const float* blin = (const float*)d_in[11];
    float* out = (float*)d_out;

    const int N = in_sizes[0] / F_IN;   // 50000
    const int E = in_sizes[1] / 2;      // 400000

    float *xl1, *xr1, *xl2, *xr2, *h1;
    float2 *xs, *h1s, *wl1s, *wr1s, *wl2s, *wr2s, *wlins;
    int *deg, *rowptr, *cursor, *csr;
    cudaGetSymbolAddress((void**)&xl1,    g_xl1);
    cudaGetSymbolAddress((void**)&xr1,    g_xr1);
    cudaGetSymbolAddress((void**)&h1,     g_h1);
    cudaGetSymbolAddress((void**)&xl2,    g_xl2);
    cudaGetSymbolAddress((void**)&xr2,    g_xr2);
    cudaGetSymbolAddress((void**)&xs,     g_xs);
    cudaGetSymbolAddress((void**)&h1s,    g_h1s);
    cudaGetSymbolAddress((void**)&wl1s,   g_wl1s);
    cudaGetSymbolAddress((void**)&wr1s,   g_wr1s);
    cudaGetSymbolAddress((void**)&wl2s,   g_wl2s);
    cudaGetSymbolAddress((void**)&wr2s,   g_wr2s);
    cudaGetSymbolAddress((void**)&wlins,  g_wlins);
    cudaGetSymbolAddress((void**)&deg,    g_deg);
    cudaGetSymbolAddress((void**)&rowptr, g_rowptr);
    cudaGetSymbolAddress((void**)&cursor, g_cursor);
    cudaGetSymbolAddress((void**)&csr,    g_csr);

    // ---- launches 1-3: pre-split layer-1 operands ----
    k_split<<<cdiv(F_IN * HEADS * HID, 256), 256>>>(Wl1, wl1s, F_IN * HEADS * HID);
    k_split<<<cdiv(F_IN * HEADS * HID, 256), 256>>>(Wr1, wr1s, F_IN * HEADS * HID);
    k_split<<<cdiv(N * F_IN, 256), 256>>>(x, xs, N * F_IN);

    // ---- launches 4-5: layer-1 GEMMs (#4 = ncu capture slot) ----
    {
        dim3 g(cdiv(HEADS * HID, 64), cdiv(N, 128));
        k_mma_s<<<g, 256>>>(xs, wl1s, xl1, N, HEADS * HID, F_IN, nullptr);
        k_mma_s<<<g, 256>>>(xs, wr1s, xr1, N, HEADS * HID, F_IN, nullptr);
    }

    // ---- residual: split Wlin, GEMM into out ----
    k_split<<<cdiv(F_IN * N_CLS, 256), 256>>>(Wlin, wlins, F_IN * N_CLS);
    {
        dim3 g(cdiv(N_CLS, 64), cdiv(N, 128));
        k_mma_s<<<g, 256>>>(xs, wlins, out, N, N_CLS, F_IN, blin);
    }

    // ---- dtype detect + CSR build ----
    k_flag_init<<<1, 1>>>();
    k_detect<<<cdiv(E, 256), 256>>>(ei, E);
    k_init_deg<<<cdiv(N, 256), 256>>>(deg, N);
    k_hist<<<cdiv(E, 256), 256>>>(ei, E, deg);
    k_scan<<<1, 1024>>>(deg, rowptr, N);
    k_cursor_self<<<cdiv(N, 256), 256>>>(rowptr, cursor, csr, N);
    k_scatter_edges<<<cdiv(E, 256), 256>>>(ei, E, cursor, csr);

    // ---- GAT layer 1 (fused, relu) -> h1 ----
    k_gatv2<HID, true, false><<<N, 256>>>(xl1, xr1, att1, b1, rowptr, csr, nullptr, h1);

    // ---- layer-2: split h1 + weights, GEMMs ----
    k_split<<<cdiv(N * HID, 256), 256>>>(h1, h1s, N * HID);
    k_split<<<cdiv(HID * HEADS * N_CLS, 256), 256>>>(Wl2, wl2s, HID * HEADS * N_CLS);
    k_split<<<cdiv(HID * HEADS * N_CLS, 256), 256>>>(Wr2, wr2s, HID * HEADS * N_CLS);
    {
        dim3 g(cdiv(HEADS * N_CLS, 64), cdiv(N, 128));
        k_mma_s<<<g, 256>>>(h1s, wl2s, xl2, N, HEADS * N_CLS, HID, nullptr);
        k_mma_s<<<g, 256>>>(h1s, wr2s, xr2, N, HEADS * N_CLS, HID, nullptr);
    }

    // ---- GAT layer 2 (fused) + residual -> out ----
    k_gatv2<N_CLS, false, true><<<N, 256>>>(xl2, xr2, att2, b2, rowptr, csr, out, out);
}

// round 11
// speedup vs baseline: 1.4031x; 1.4031x over previous
#include <cuda_runtime.h>
#include <cuda_fp16.h>
#include <cstdint>

// ---------------------------------------------------------------------------
// Problem constants
// ---------------------------------------------------------------------------
#define N_NODES 50000
#define N_EDGES 400000
#define F_IN    256
#define HID     64
#define N_CLS   32
#define HEADS   8

// ---------------------------------------------------------------------------
// Static scratch. xl/xr plain row-major [node][h*c] (R7 fused-gat layout).
// *_h/_l are fp16 hi/lo planes. Weight planes stored TRANSPOSED [n][k].
// ---------------------------------------------------------------------------
__device__ float  g_xl1[N_NODES * HEADS * HID];    // 102.4 MB
__device__ float  g_xr1[N_NODES * HEADS * HID];    // 102.4 MB
__device__ float  g_h1 [N_NODES * HID];            // 12.8 MB
__device__ float  g_xl2[N_NODES * HEADS * N_CLS];  // 51.2 MB
__device__ float  g_xr2[N_NODES * HEADS * N_CLS];  // 51.2 MB
__device__ __half g_xh [N_NODES * F_IN];           // 25.6 MB
__device__ __half g_xlo[N_NODES * F_IN];           // 25.6 MB
__device__ __half g_h1h[N_NODES * HID];            // 6.4 MB
__device__ __half g_h1l[N_NODES * HID];            // 6.4 MB
__device__ __half g_w1lh[HEADS * HID * F_IN], g_w1ll[HEADS * HID * F_IN];   // [512][256]
__device__ __half g_w1rh[HEADS * HID * F_IN], g_w1rl[HEADS * HID * F_IN];
__device__ __half g_w2lh[HEADS * N_CLS * HID], g_w2ll[HEADS * N_CLS * HID]; // [256][64]
__device__ __half g_w2rh[HEADS * N_CLS * HID], g_w2rl[HEADS * N_CLS * HID];
__device__ __half g_wlih[N_CLS * F_IN], g_wlil[N_CLS * F_IN];               // [32][256]
__device__ int    g_deg   [N_NODES];
__device__ int    g_rowptr[N_NODES + 1];
__device__ int    g_cursor[N_NODES];
__device__ int    g_csr   [N_EDGES + N_NODES];
__device__ int    g_is64;

// ---------------------------------------------------------------------------
// fp16 hi/lo split kernels (one-time, out of the GEMM hot loop)
// ---------------------------------------------------------------------------
__global__ void k_split_row(const float* __restrict__ in,
                            __half* __restrict__ hi, __half* __restrict__ lo, int n) {
    int i = blockIdx.x * blockDim.x + threadIdx.x;
    if (i < n) {
        float v = in[i];
        __half h = __float2half_rn(v);
        hi[i] = h;
        lo[i] = __float2half_rn(v - __half2float(h));
    }
}

// B [K][N] row-major fp32 -> transposed planes [N][K] fp16
__global__ void k_split_bt(const float* __restrict__ B,
                           __half* __restrict__ hiT, __half* __restrict__ loT,
                           int K, int N) {
    int i = blockIdx.x * blockDim.x + threadIdx.x;
    if (i < K * N) {
        int k = i / N, n = i % N;
        float v = B[i];
        __half h = __float2half_rn(v);
        hiT[(size_t)n * K + k] = h;
        loT[(size_t)n * K + k] = __float2half_rn(v - __half2float(h));
    }
}

// ---------------------------------------------------------------------------
// edge_index dtype probe (int64 => all high words zero since ids < 2^31).
// ---------------------------------------------------------------------------
__global__ void k_flag_init() { g_is64 = 1; }

__global__ void k_detect(const int* __restrict__ p, int nPairs) {
    int i = blockIdx.x * blockDim.x + threadIdx.x;
    if (i < nPairs && p[2 * i + 1] != 0) g_is64 = 0;   // benign race: only writes 0
}

__device__ __forceinline__ int edge_at(const int* __restrict__ p, int e) {
    if (g_is64) return (int)(((const long long*)p)[e]);
    return p[e];
}

// ---------------------------------------------------------------------------
// CSR build (dst-major, self loops first, range-guarded)
// ---------------------------------------------------------------------------
__global__ void k_init_deg(int* __restrict__ deg, int n) {
    int i = blockIdx.x * blockDim.x + threadIdx.x;
    if (i < n) deg[i] = 1;
}

__global__ void k_hist(const int* __restrict__ ei, int E, int* __restrict__ deg) {
    int e = blockIdx.x * blockDim.x + threadIdx.x;
    if (e < E) {
        unsigned d = (unsigned)edge_at(ei, E + e);
        unsigned s = (unsigned)edge_at(ei, e);
        if (d < (unsigned)N_NODES && s < (unsigned)N_NODES)
            atomicAdd(&deg[d], 1);
    }
}

__global__ void k_scan(const int* __restrict__ deg, int* __restrict__ rowptr, int n) {
    __shared__ int sm[1024];
    __shared__ int s_carry;
    int t = threadIdx.x;
    if (t == 0) s_carry = 0;
    __syncthreads();
    for (int base = 0; base < n; base += 1024) {
        int i = base + t;
        int v = (i < n) ? deg[i] : 0;
        sm[t] = v;
        __syncthreads();
        #pragma unroll
        for (int off = 1; off < 1024; off <<= 1) {
            int add = (t >= off) ? sm[t - off] : 0;
            __syncthreads();
            sm[t] += add;
            __syncthreads();
        }
        int incl = sm[t];
        int carry = s_carry;
        if (i < n) rowptr[i] = carry + incl - v;
        __syncthreads();
        if (t == 1023) s_carry = carry + incl;
        __syncthreads();
    }
    if (t == 0) rowptr[n] = s_carry;
}

__global__ void k_cursor_self(const int* __restrict__ rowptr, int* __restrict__ cur,
                              int* __restrict__ csr, int n) {
    int i = blockIdx.x * blockDim.x + threadIdx.x;
    if (i < n) {
        int p = rowptr[i];
        csr[p] = i;
        cur[i] = p + 1;
    }
}

__global__ void k_scatter_edges(const int* __restrict__ ei, int E,
                                int* __restrict__ cur, int* __restrict__ csr) {
    int e = blockIdx.x * blockDim.x + threadIdx.x;
    if (e < E) {
        unsigned s = (unsigned)edge_at(ei, e);
        unsigned d = (unsigned)edge_at(ei, E + e);
        if (d < (unsigned)N_NODES && s < (unsigned)N_NODES)
            csr[atomicAdd(&cur[d], 1)] = (int)s;
    }
}

// ---------------------------------------------------------------------------
// fp16 2-term compensated tensor GEMM.
// C[M,N] = A[M,K] @ B[K,N] (+bias) with A,B pre-split into fp16 hi/lo planes;
// B planes TRANSPOSED [n][k]. A*B ~= ahi*bhi + ahi*blo + alo*bhi (fp32 acc).
// Block 128x64x16, 8 warps (4Mx2N), warp tile 32x32 (2 mfrag x 4 nfrag of
// m16n8k16). cp.async double buffer. K%16==0.
// ---------------------------------------------------------------------------
__device__ __forceinline__ void mma_f16(float* c, const unsigned* a, const unsigned* b) {
    asm volatile(
        "mma.sync.aligned.m16n8k16.row.col.f32.f16.f16.f32 "
        "{%0,%1,%2,%3}, {%4,%5,%6,%7}, {%8,%9}, {%0,%1,%2,%3};"
        : "+f"(c[0]), "+f"(c[1]), "+f"(c[2]), "+f"(c[3])
        : "r"(a[0]), "r"(a[1]), "r"(a[2]), "r"(a[3]), "r"(b[0]), "r"(b[1]));
}

__device__ __forceinline__ void cp16(void* dst_smem, const void* src, bool pred) {
    unsigned saddr = (unsigned)__cvta_generic_to_shared(dst_smem);
    int sz = pred ? 16 : 0;
    asm volatile("cp.async.cg.shared.global [%0], [%1], 16, %2;"
                 :: "r"(saddr), "l"(src), "r"(sz));
}

__device__ __forceinline__ unsigned lds32(const __half* p) {
    return *reinterpret_cast<const unsigned*>(p);
}

__global__ void __launch_bounds__(256)
k_mma_h(const __half* __restrict__ Ah, const __half* __restrict__ Al,
        const __half* __restrict__ Bth, const __half* __restrict__ Btl,
        float* __restrict__ C, int M, int N, int K,
        const float* __restrict__ bias) {
    constexpr int BM = 128, BN = 64, BK = 16;
    constexpr int SA = 24;   // half-stride: 48B rows (12 words -> conflict-free frags)
    __shared__ __align__(16) __half sAh[2][BM][SA];   // 12288 B
    __shared__ __align__(16) __half sAl[2][BM][SA];   // 12288 B
    __shared__ __align__(16) __half sBh[2][BN][SA];   //  6144 B
    __shared__ __align__(16) __half sBl[2][BN][SA];   //  6144 B  (total 36864 B)

    const int tid  = threadIdx.x;
    const int lane = tid & 31;
    const int wid  = tid >> 5;
    const int warpM = wid >> 1;
    const int warpN = wid & 1;
    const int gid = lane >> 2;      // 0..7
    const int tig = lane & 3;       // 0..3

    const int bm = blockIdx.y * BM;
    const int bn = blockIdx.x * BN;

    // cp.async assignments: A planes 128 rows x 2 x 16B chunks
    const int aRow = tid >> 1;              // 0..127
    const int aChunk = (tid & 1) * 8;       // half offset 0 or 8
    const bool aOk = (bm + aRow) < M;
    // B planes: 64 rows x 2 chunks = 128 cp16 per plane
    const int bRow = (tid & 127) >> 1;      // 0..63 (n-index)
    const int bChunk = (tid & 1) * 8;
    const bool bIsHi = tid < 128;
    const bool bOk = (bn + bRow) < N;

    float acc[2][4][4];
    #pragma unroll
    for (int i = 0; i < 2; ++i)
        #pragma unroll
        for (int j = 0; j < 4; ++j)
            #pragma unroll
            for (int r = 0; r < 4; ++r) acc[i][j][r] = 0.f;

    const int nt = K / BK;
    const __half* aHB = Ah + (size_t)(bm + aRow) * K;
    const __half* aLB = Al + (size_t)(bm + aRow) * K;
    const __half* bP  = (bIsHi ? Bth : Btl) + (size_t)(bn + bRow) * K;

    // prologue: tile 0
    cp16(&sAh[0][aRow][aChunk], aOk ? (const void*)(aHB + aChunk) : (const void*)Ah, aOk);
    cp16(&sAl[0][aRow][aChunk], aOk ? (const void*)(aLB + aChunk) : (const void*)Al, aOk);
    {
        void* dst = bIsHi ? (void*)&sBh[0][bRow][bChunk] : (void*)&sBl[0][bRow][bChunk];
        cp16(dst, bOk ? (const void*)(bP + bChunk) : (const void*)Bth, bOk);
    }
    asm volatile("cp.async.commit_group;");
    asm volatile("cp.async.wait_group 0;" ::: "memory");
    __syncthreads();

    for (int t = 0; t < nt; ++t) {
        const int cur = t & 1;
        if (t + 1 < nt) {
            const int k0 = (t + 1) * BK;
            const int nxt = cur ^ 1;
            cp16(&sAh[nxt][aRow][aChunk], aOk ? (const void*)(aHB + k0 + aChunk) : (const void*)Ah, aOk);
            cp16(&sAl[nxt][aRow][aChunk], aOk ? (const void*)(aLB + k0 + aChunk) : (const void*)Al, aOk);
            void* dst = bIsHi ? (void*)&sBh[nxt][bRow][bChunk] : (void*)&sBl[nxt][bRow][bChunk];
            cp16(dst, bOk ? (const void*)(bP + k0 + bChunk) : (const void*)Bth, bOk);
            asm volatile("cp.async.commit_group;");
        }

        // fragment loads (all single LDS.32, conflict-free at stride 12 words)
        unsigned ahi[2][4], alo[2][4], bhi[4][2], blo[4][2];
        #pragma unroll
        for (int mf = 0; mf < 2; ++mf) {
            const int mb = warpM * 32 + mf * 16;
            ahi[mf][0] = lds32(&sAh[cur][mb + gid    ][2 * tig]);
            ahi[mf][1] = lds32(&sAh[cur][mb + gid + 8][2 * tig]);
            ahi[mf][2] = lds32(&sAh[cur][mb + gid    ][2 * tig + 8]);
            ahi[mf][3] = lds32(&sAh[cur][mb + gid + 8][2 * tig + 8]);
            alo[mf][0] = lds32(&sAl[cur][mb + gid    ][2 * tig]);
            alo[mf][1] = lds32(&sAl[cur][mb + gid + 8][2 * tig]);
            alo[mf][2] = lds32(&sAl[cur][mb + gid    ][2 * tig + 8]);
            alo[mf][3] = lds32(&sAl[cur][mb + gid + 8][2 * tig + 8]);
        }
        #pragma unroll
        for (int nf = 0; nf < 4; ++nf) {
            const int nb = warpN * 32 + nf * 8;
            bhi[nf][0] = lds32(&sBh[cur][nb + gid][2 * tig]);
            bhi[nf][1] = lds32(&sBh[cur][nb + gid][2 * tig + 8]);
            blo[nf][0] = lds32(&sBl[cur][nb + gid][2 * tig]);
            blo[nf][1] = lds32(&sBl[cur][nb + gid][2 * tig + 8]);
        }

        #pragma unroll
        for (int mf = 0; mf < 2; ++mf)
            #pragma unroll
            for (int nf = 0; nf < 4; ++nf) {
                mma_f16(acc[mf][nf], alo[mf], bhi[nf]);
                mma_f16(acc[mf][nf], ahi[mf], blo[nf]);
                mma_f16(acc[mf][nf], ahi[mf], bhi[nf]);
            }

        if (t + 1 < nt) {
            asm volatile("cp.async.wait_group 0;" ::: "memory");
            __syncthreads();
        }
    }

    // epilogue (c0..c3: rows gid/gid+8, cols 2tig/2tig+1)
    #pragma unroll
    for (int mf = 0; mf < 2; ++mf) {
        #pragma unroll
        for (int nf = 0; nf < 4; ++nf) {
            const int col0 = bn + warpN * 32 + nf * 8 + 2 * tig;
            const int row0 = bm + warpM * 32 + mf * 16 + gid;
            #pragma unroll
            for (int half = 0; half < 2; ++half) {
                const int row = row0 + half * 8;
                if (row >= M) continue;
                #pragma unroll
                for (int c = 0; c < 2; ++c) {
                    const int col = col0 + c;
                    if (col < N) {
                        float v = acc[mf][nf][half * 2 + c];
                        if (bias) v += bias[col];
                        C[(size_t)row * N + col] = v;
                    }
                }
            }
        }
    }
}

// ---------------------------------------------------------------------------
// GATv2 edge+softmax+aggregate, fused per dst node (R7 known-best form).
// ---------------------------------------------------------------------------
template <int C, bool RELU, bool ADD_RES>
__global__ void __launch_bounds__(256)
k_gatv2(const float* __restrict__ xl, const float* __restrict__ xr,
        const float* __restrict__ att, const float* __restrict__ bias,
        const int* __restrict__ rowptr, const int* __restrict__ csr,
        const float* __restrict__ resid, float* __restrict__ out) {
    constexpr int H = HEADS;
    constexpr int KC = C / 32;
    int node = blockIdx.x;
    int w = threadIdx.x >> 5;
    int l = threadIdx.x & 31;

    const float* xr_row = xr + (size_t)node * H * C + w * C;
    float xrv[KC], attv[KC], accv[KC];
    #pragma unroll
    for (int k = 0; k < KC; ++k) {
        xrv[k]  = xr_row[l + 32 * k];
        attv[k] = att[w * C + l + 32 * k];
        accv[k] = 0.f;
    }
    float denom = 0.f;

    int beg = rowptr[node], end = rowptr[node + 1];
    for (int idx = beg; idx < end; ++idx) {
        int s = csr[idx];
        const float* xl_row = xl + (size_t)s * H * C + w * C;
        float xlv[KC];
        float partial = 0.f;
        #pragma unroll
        for (int k = 0; k < KC; ++k) {
            xlv[k] = xl_row[l + 32 * k];
            float v = xlv[k] + xrv[k];
            v = (v > 0.f) ? v : 0.2f * v;      // leaky_relu(0.2)
            partial = fmaf(attv[k], v, partial);
        }
        #pragma unroll
        for (int off = 16; off > 0; off >>= 1)
            partial += __shfl_xor_sync(0xffffffffu, partial, off);
        float p = __expf(partial);
        denom += p;
        #pragma unroll
        for (int k = 0; k < KC; ++k)
            accv[k] = fmaf(p, xlv[k], accv[k]);
    }

    __shared__ float sh[H * C];
    float inv = 1.f / denom;
    #pragma unroll
    for (int k = 0; k < KC; ++k)
        sh[w * C + l + 32 * k] = accv[k] * inv;
    __syncthreads();

    if (threadIdx.x < C) {
        int c = threadIdx.x;
        float s = 0.f;
        #pragma unroll
        for (int h = 0; h < H; ++h) s += sh[h * C + c];
        s = s * (1.f / H) + bias[c];
        if (RELU) s = fmaxf(s, 0.f);
        if (ADD_RES) s += resid[(size_t)node * C + c];
        out[(size_t)node * C + c] = s;
    }
}

// ---------------------------------------------------------------------------
// Launch. First big GEMM at launch #4 (ncu's observed capture slot).
// ---------------------------------------------------------------------------
static inline int cdiv(int a, int b) { return (a + b - 1) / b; }

extern "C" void kernel_launch(void* const* d_in, const int* in_sizes, int n_in,
                              void* d_out, int out_size) {
    const float* x    = (const float*)d_in[0];
    const int*   ei   = (const int*)d_in[1];
    const float* Wl1  = (const float*)d_in[2];
    const float* Wr1  = (const float*)d_in[3];
    const float* att1 = (const float*)d_in[4];
    const float* b1   = (const float*)d_in[5];
    const float* Wl2  = (const float*)d_in[6];
    const float* Wr2  = (const float*)d_in[7];
    const float* att2 = (const float*)d_in[8];
    const float* b2   = (const float*)d_in[9];
    const float* Wlin = (const float*)d_in[10];
    const float* blin = (const float*)d_in[11];
    float* out = (float*)d_out;

    const int N = in_sizes[0] / F_IN;   // 50000
    const int E = in_sizes[1] / 2;      // 400000

    float *xl1, *xr1, *xl2, *xr2, *h1;
    __half *xh, *xlo, *h1h, *h1l;
    __half *w1lh, *w1ll, *w1rh, *w1rl, *w2lh, *w2ll, *w2rh, *w2rl, *wlih, *wlil;
    int *deg, *rowptr, *cursor, *csr;
    cudaGetSymbolAddress((void**)&xl1,    g_xl1);
    cudaGetSymbolAddress((void**)&xr1,    g_xr1);
    cudaGetSymbolAddress((void**)&h1,     g_h1);
    cudaGetSymbolAddress((void**)&xl2,    g_xl2);
    cudaGetSymbolAddress((void**)&xr2,    g_xr2);
    cudaGetSymbolAddress((void**)&xh,     g_xh);
    cudaGetSymbolAddress((void**)&xlo,    g_xlo);
    cudaGetSymbolAddress((void**)&h1h,    g_h1h);
    cudaGetSymbolAddress((void**)&h1l,    g_h1l);
    cudaGetSymbolAddress((void**)&w1lh,   g_w1lh);
    cudaGetSymbolAddress((void**)&w1ll,   g_w1ll);
    cudaGetSymbolAddress((void**)&w1rh,   g_w1rh);
    cudaGetSymbolAddress((void**)&w1rl,   g_w1rl);
    cudaGetSymbolAddress((void**)&w2lh,   g_w2lh);
    cudaGetSymbolAddress((void**)&w2ll,   g_w2ll);
    cudaGetSymbolAddress((void**)&w2rh,   g_w2rh);
    cudaGetSymbolAddress((void**)&w2rl,   g_w2rl);
    cudaGetSymbolAddress((void**)&wlih,   g_wlih);
    cudaGetSymbolAddress((void**)&wlil,   g_wlil);
    cudaGetSymbolAddress((void**)&deg,    g_deg);
    cudaGetSymbolAddress((void**)&rowptr, g_rowptr);
    cudaGetSymbolAddress((void**)&cursor, g_cursor);
    cudaGetSymbolAddress((void**)&csr,    g_csr);

    // ---- launches 1-3: pre-split layer-1 operands ----
    k_split_bt<<<cdiv(F_IN * HEADS * HID, 256), 256>>>(Wl1, w1lh, w1ll, F_IN, HEADS * HID);
    k_split_bt<<<cdiv(F_IN * HEADS * HID, 256), 256>>>(Wr1, w1rh, w1rl, F_IN, HEADS * HID);
    k_split_row<<<cdiv(N * F_IN, 256), 256>>>(x, xh, xlo, N * F_IN);

    // ---- launches 4-5: layer-1 GEMMs (#4 = ncu capture slot) ----
    {
        dim3 g(cdiv(HEADS * HID, 64), cdiv(N, 128));
        k_mma_h<<<g, 256>>>(xh, xlo, w1lh, w1ll, xl1, N, HEADS * HID, F_IN, nullptr);
        k_mma_h<<<g, 256>>>(xh, xlo, w1rh, w1rl, xr1, N, HEADS * HID, F_IN, nullptr);
    }

    // ---- residual GEMM into out ----
    k_split_bt<<<cdiv(F_IN * N_CLS, 256), 256>>>(Wlin, wlih, wlil, F_IN, N_CLS);
    {
        dim3 g(cdiv(N_CLS, 64), cdiv(N, 128));
        k_mma_h<<<g, 256>>>(xh, xlo, wlih, wlil, out, N, N_CLS, F_IN, blin);
    }

    // ---- dtype detect + CSR build ----
    k_flag_init<<<1, 1>>>();
    k_detect<<<cdiv(E, 256), 256>>>(ei, E);
    k_init_deg<<<cdiv(N, 256), 256>>>(deg, N);
    k_hist<<<cdiv(E, 256), 256>>>(ei, E, deg);
    k_scan<<<1, 1024>>>(deg, rowptr, N);
    k_cursor_self<<<cdiv(N, 256), 256>>>(rowptr, cursor, csr, N);
    k_scatter_edges<<<cdiv(E, 256), 256>>>(ei, E, cursor, csr);

    // ---- GAT layer 1 (fused, relu) -> h1 ----
    k_gatv2<HID, true, false><<<N, 256>>>(xl1, xr1, att1, b1, rowptr, csr, nullptr, h1);

    // ---- layer-2: split h1 + weights, GEMMs ----
    k_split_row<<<cdiv(N * HID, 256), 256>>>(h1, h1h, h1l, N * HID);
    k_split_bt<<<cdiv(HID * HEADS * N_CLS, 256), 256>>>(Wl2, w2lh, w2ll, HID, HEADS * N_CLS);
    k_split_bt<<<cdiv(HID * HEADS * N_CLS, 256), 256>>>(Wr2, w2rh, w2rl, HID, HEADS * N_CLS);
    {
        dim3 g(cdiv(HEADS * N_CLS, 64), cdiv(N, 128));
        k_mma_h<<<g, 256>>>(h1h, h1l, w2lh, w2ll, xl2, N, HEADS * N_CLS, HID, nullptr);
        k_mma_h<<<g, 256>>>(h1h, h1l, w2rh, w2rl, xr2, N, HEADS * N_CLS, HID, nullptr);
    }

    // ---- GAT layer 2 (fused) + residual -> out ----
    k_gatv2<N_CLS, false, true><<<N, 256>>>(xl2, xr2, att2, b2, rowptr, csr, out, out);
}

// round 12
// speedup vs baseline: 1.5080x; 1.0748x over previous
#include <cuda_runtime.h>
#include <cuda_fp16.h>
#include <cstdint>

// ---------------------------------------------------------------------------
// Problem constants
// ---------------------------------------------------------------------------
#define N_NODES 50000
#define N_EDGES 400000
#define F_IN    256
#define HID     64
#define N_CLS   32
#define HEADS   8

// ---------------------------------------------------------------------------
// Static scratch.
// x1: combined layer-1 activations [node][xl(512) | xr(512)]
// x2: combined layer-2 activations [node][xl(256) | xr(256)]
// Weight planes fp16 hi/lo, TRANSPOSED [n][k], L and R halves side by side.
// ---------------------------------------------------------------------------
__device__ float  g_x1 [N_NODES * 2 * HEADS * HID];    // 204.8 MB
__device__ float  g_x2 [N_NODES * 2 * HEADS * N_CLS];  // 102.4 MB
__device__ float  g_h1 [N_NODES * HID];                // 12.8 MB
__device__ __half g_xh [N_NODES * F_IN];               // 25.6 MB
__device__ __half g_xlo[N_NODES * F_IN];               // 25.6 MB
__device__ __half g_h1h[N_NODES * HID];                // 6.4 MB
__device__ __half g_h1l[N_NODES * HID];                // 6.4 MB
__device__ __half g_w1h[2 * HEADS * HID * F_IN], g_w1l[2 * HEADS * HID * F_IN]; // [1024][256]
__device__ __half g_w2h[2 * HEADS * N_CLS * HID], g_w2l[2 * HEADS * N_CLS * HID]; // [512][64]
__device__ __half g_wlih[N_CLS * F_IN], g_wlil[N_CLS * F_IN];                   // [32][256]
__device__ int    g_deg   [N_NODES];
__device__ int    g_rowptr[N_NODES + 1];
__device__ int    g_cursor[N_NODES];
__device__ int    g_csr   [N_EDGES + N_NODES];
__device__ int    g_is64;

// ---------------------------------------------------------------------------
// fp16 hi/lo split kernels (one-time, out of the GEMM hot loop)
// ---------------------------------------------------------------------------
__global__ void k_split_row(const float* __restrict__ in,
                            __half* __restrict__ hi, __half* __restrict__ lo, int n) {
    int i = blockIdx.x * blockDim.x + threadIdx.x;
    if (i < n) {
        float v = in[i];
        __half h = __float2half_rn(v);
        hi[i] = h;
        lo[i] = __float2half_rn(v - __half2float(h));
    }
}

// B [K][N] row-major fp32 -> transposed planes [N][K] fp16
__global__ void k_split_bt(const float* __restrict__ B,
                           __half* __restrict__ hiT, __half* __restrict__ loT,
                           int K, int N) {
    int i = blockIdx.x * blockDim.x + threadIdx.x;
    if (i < K * N) {
        int k = i / N, n = i % N;
        float v = B[i];
        __half h = __float2half_rn(v);
        hiT[(size_t)n * K + k] = h;
        loT[(size_t)n * K + k] = __float2half_rn(v - __half2float(h));
    }
}

// ---------------------------------------------------------------------------
// edge_index dtype probe (int64 => all high words zero since ids < 2^31).
// ---------------------------------------------------------------------------
__global__ void k_flag_init() { g_is64 = 1; }

__global__ void k_detect(const int* __restrict__ p, int nPairs) {
    int i = blockIdx.x * blockDim.x + threadIdx.x;
    if (i < nPairs && p[2 * i + 1] != 0) g_is64 = 0;   // benign race: only writes 0
}

__device__ __forceinline__ int edge_at(const int* __restrict__ p, int e) {
    if (g_is64) return (int)(((const long long*)p)[e]);
    return p[e];
}

// ---------------------------------------------------------------------------
// CSR build (dst-major, self loops first, range-guarded)
// ---------------------------------------------------------------------------
__global__ void k_init_deg(int* __restrict__ deg, int n) {
    int i = blockIdx.x * blockDim.x + threadIdx.x;
    if (i < n) deg[i] = 1;
}

__global__ void k_hist(const int* __restrict__ ei, int E, int* __restrict__ deg) {
    int e = blockIdx.x * blockDim.x + threadIdx.x;
    if (e < E) {
        unsigned d = (unsigned)edge_at(ei, E + e);
        unsigned s = (unsigned)edge_at(ei, e);
        if (d < (unsigned)N_NODES && s < (unsigned)N_NODES)
            atomicAdd(&deg[d], 1);
    }
}

__global__ void k_scan(const int* __restrict__ deg, int* __restrict__ rowptr, int n) {
    __shared__ int sm[1024];
    __shared__ int s_carry;
    int t = threadIdx.x;
    if (t == 0) s_carry = 0;
    __syncthreads();
    for (int base = 0; base < n; base += 1024) {
        int i = base + t;
        int v = (i < n) ? deg[i] : 0;
        sm[t] = v;
        __syncthreads();
        #pragma unroll
        for (int off = 1; off < 1024; off <<= 1) {
            int add = (t >= off) ? sm[t - off] : 0;
            __syncthreads();
            sm[t] += add;
            __syncthreads();
        }
        int incl = sm[t];
        int carry = s_carry;
        if (i < n) rowptr[i] = carry + incl - v;
        __syncthreads();
        if (t == 1023) s_carry = carry + incl;
        __syncthreads();
    }
    if (t == 0) rowptr[n] = s_carry;
}

__global__ void k_cursor_self(const int* __restrict__ rowptr, int* __restrict__ cur,
                              int* __restrict__ csr, int n) {
    int i = blockIdx.x * blockDim.x + threadIdx.x;
    if (i < n) {
        int p = rowptr[i];
        csr[p] = i;
        cur[i] = p + 1;
    }
}

__global__ void k_scatter_edges(const int* __restrict__ ei, int E,
                                int* __restrict__ cur, int* __restrict__ csr) {
    int e = blockIdx.x * blockDim.x + threadIdx.x;
    if (e < E) {
        unsigned s = (unsigned)edge_at(ei, e);
        unsigned d = (unsigned)edge_at(ei, E + e);
        if (d < (unsigned)N_NODES && s < (unsigned)N_NODES)
            csr[atomicAdd(&cur[d], 1)] = (int)s;
    }
}

// ---------------------------------------------------------------------------
// fp16 2-term compensated tensor GEMM (ldmatrix fragments).
// C[M,N] = A[M,K] @ B[K,N] (+bias); A,B pre-split fp16 hi/lo planes; B planes
// TRANSPOSED [n][k]. A*B ~= ahi*bhi + ahi*blo + alo*bhi, fp32 accum.
// Block 128x64x16, 8 warps (4Mx2N), warp tile 32x32. cp.async double buffer.
// ---------------------------------------------------------------------------
__device__ __forceinline__ void mma_f16(float* c, const unsigned* a, const unsigned* b) {
    asm volatile(
        "mma.sync.aligned.m16n8k16.row.col.f32.f16.f16.f32 "
        "{%0,%1,%2,%3}, {%4,%5,%6,%7}, {%8,%9}, {%0,%1,%2,%3};"
        : "+f"(c[0]), "+f"(c[1]), "+f"(c[2]), "+f"(c[3])
        : "r"(a[0]), "r"(a[1]), "r"(a[2]), "r"(a[3]), "r"(b[0]), "r"(b[1]));
}

__device__ __forceinline__ void cp16(void* dst_smem, const void* src, bool pred) {
    unsigned saddr = (unsigned)__cvta_generic_to_shared(dst_smem);
    int sz = pred ? 16 : 0;
    asm volatile("cp.async.cg.shared.global [%0], [%1], 16, %2;"
                 :: "r"(saddr), "l"(src), "r"(sz));
}

__device__ __forceinline__ void ldsm4(unsigned* r, const __half* p) {
    unsigned a = (unsigned)__cvta_generic_to_shared(p);
    asm volatile("ldmatrix.sync.aligned.m8n8.x4.shared.b16 {%0,%1,%2,%3}, [%4];"
                 : "=r"(r[0]), "=r"(r[1]), "=r"(r[2]), "=r"(r[3]) : "r"(a));
}

__global__ void __launch_bounds__(256)
k_mma_h(const __half* __restrict__ Ah, const __half* __restrict__ Al,
        const __half* __restrict__ Bth, const __half* __restrict__ Btl,
        float* __restrict__ C, int M, int N, int K,
        const float* __restrict__ bias) {
    constexpr int BM = 128, BN = 64, BK = 16;
    constexpr int SA = 24;   // half-stride: 48B rows -> ldmatrix conflict-free
    __shared__ __align__(16) __half sAh[2][BM][SA];
    __shared__ __align__(16) __half sAl[2][BM][SA];
    __shared__ __align__(16) __half sBh[2][BN][SA];
    __shared__ __align__(16) __half sBl[2][BN][SA];   // total 36864 B

    const int tid  = threadIdx.x;
    const int lane = tid & 31;
    const int wid  = tid >> 5;
    const int warpM = wid >> 1;
    const int warpN = wid & 1;
    const int tig = lane & 3;

    const int bm = blockIdx.y * BM;
    const int bn = blockIdx.x * BN;

    // cp.async assignments
    const int aRow = tid >> 1;              // 0..127
    const int aChunk = (tid & 1) * 8;       // half offset 0 or 8
    const bool aOk = (bm + aRow) < M;
    const int bRow = (tid & 127) >> 1;      // 0..63 (n-index)
    const int bChunk = (tid & 1) * 8;
    const bool bIsHi = tid < 128;
    const bool bOk = (bn + bRow) < N;

    // ldmatrix source offsets (per-lane)
    const int aLdRow = lane & 15;           // m within 16-row frag
    const int aLdCol = (lane >> 4) * 8;     // k 0 or 8
    const int bLdRow = lane & 7;            // n within 8-row matrix
    const int bLdSel = (lane >> 4) & 1;     // nf pair member
    const int bLdCol = ((lane >> 3) & 1) * 8;

    float acc[2][4][4];
    #pragma unroll
    for (int i = 0; i < 2; ++i)
        #pragma unroll
        for (int j = 0; j < 4; ++j)
            #pragma unroll
            for (int r = 0; r < 4; ++r) acc[i][j][r] = 0.f;

    const int nt = K / BK;
    const __half* aHB = Ah + (size_t)(bm + aRow) * K;
    const __half* aLB = Al + (size_t)(bm + aRow) * K;
    const __half* bP  = (bIsHi ? Bth : Btl) + (size_t)(bn + bRow) * K;

    cp16(&sAh[0][aRow][aChunk], aOk ? (const void*)(aHB + aChunk) : (const void*)Ah, aOk);
    cp16(&sAl[0][aRow][aChunk], aOk ? (const void*)(aLB + aChunk) : (const void*)Al, aOk);
    {
        void* dst = bIsHi ? (void*)&sBh[0][bRow][bChunk] : (void*)&sBl[0][bRow][bChunk];
        cp16(dst, bOk ? (const void*)(bP + bChunk) : (const void*)Bth, bOk);
    }
    asm volatile("cp.async.commit_group;");
    asm volatile("cp.async.wait_group 0;" ::: "memory");
    __syncthreads();

    for (int t = 0; t < nt; ++t) {
        const int cur = t & 1;
        if (t + 1 < nt) {
            const int k0 = (t + 1) * BK;
            const int nxt = cur ^ 1;
            cp16(&sAh[nxt][aRow][aChunk], aOk ? (const void*)(aHB + k0 + aChunk) : (const void*)Ah, aOk);
            cp16(&sAl[nxt][aRow][aChunk], aOk ? (const void*)(aLB + k0 + aChunk) : (const void*)Al, aOk);
            void* dst = bIsHi ? (void*)&sBh[nxt][bRow][bChunk] : (void*)&sBl[nxt][bRow][bChunk];
            cp16(dst, bOk ? (const void*)(bP + k0 + bChunk) : (const void*)Bth, bOk);
            asm volatile("cp.async.commit_group;");
        }

        // ---- fragment loads: 8 ldmatrix.x4 total ----
        unsigned ahi[2][4], alo[2][4], bfh[2][4], bfl[2][4];  // bf*[jp] = {nf0 b0,b1, nf1 b0,b1}
        #pragma unroll
        for (int mf = 0; mf < 2; ++mf) {
            const int mb = warpM * 32 + mf * 16;
            ldsm4(ahi[mf], &sAh[cur][mb + aLdRow][aLdCol]);
            ldsm4(alo[mf], &sAl[cur][mb + aLdRow][aLdCol]);
        }
        #pragma unroll
        for (int jp = 0; jp < 2; ++jp) {
            const int nb = warpN * 32 + jp * 16 + bLdSel * 8 + bLdRow;
            ldsm4(bfh[jp], &sBh[cur][nb][bLdCol]);
            ldsm4(bfl[jp], &sBl[cur][nb][bLdCol]);
        }

        #pragma unroll
        for (int mf = 0; mf < 2; ++mf)
            #pragma unroll
            for (int jp = 0; jp < 2; ++jp)
                #pragma unroll
                for (int half = 0; half < 2; ++half) {
                    float* c = acc[mf][jp * 2 + half];
                    mma_f16(c, alo[mf], &bfh[jp][half * 2]);
                    mma_f16(c, ahi[mf], &bfl[jp][half * 2]);
                    mma_f16(c, ahi[mf], &bfh[jp][half * 2]);
                }

        if (t + 1 < nt) {
            asm volatile("cp.async.wait_group 0;" ::: "memory");
            __syncthreads();
        }
    }

    const int gid = lane >> 2;
    #pragma unroll
    for (int mf = 0; mf < 2; ++mf) {
        #pragma unroll
        for (int nf = 0; nf < 4; ++nf) {
            const int col0 = bn + warpN * 32 + nf * 8 + 2 * tig;
            const int row0 = bm + warpM * 32 + mf * 16 + gid;
            #pragma unroll
            for (int half = 0; half < 2; ++half) {
                const int row = row0 + half * 8;
                if (row >= M) continue;
                #pragma unroll
                for (int c = 0; c < 2; ++c) {
                    const int col = col0 + c;
                    if (col < N) {
                        float v = acc[mf][nf][half * 2 + c];
                        if (bias) v += bias[col];
                        C[(size_t)row * N + col] = v;
                    }
                }
            }
        }
    }
}

// ---------------------------------------------------------------------------
// GATv2 edge+softmax+aggregate, fused per dst node. RS = row stride of the
// combined activation array (xl/xr are slices of one [node][2*H*C] buffer).
// ---------------------------------------------------------------------------
template <int C, int RS, bool RELU, bool ADD_RES>
__global__ void __launch_bounds__(256)
k_gatv2(const float* __restrict__ xl, const float* __restrict__ xr,
        const float* __restrict__ att, const float* __restrict__ bias,
        const int* __restrict__ rowptr, const int* __restrict__ csr,
        const float* __restrict__ resid, float* __restrict__ out) {
    constexpr int H = HEADS;
    constexpr int KC = C / 32;
    int node = blockIdx.x;
    int w = threadIdx.x >> 5;
    int l = threadIdx.x & 31;

    const float* xr_row = xr + (size_t)node * RS + w * C;
    float xrv[KC], attv[KC], accv[KC];
    #pragma unroll
    for (int k = 0; k < KC; ++k) {
        xrv[k]  = xr_row[l + 32 * k];
        attv[k] = att[w * C + l + 32 * k];
        accv[k] = 0.f;
    }
    float denom = 0.f;

    int beg = rowptr[node], end = rowptr[node + 1];
    for (int idx = beg; idx < end; ++idx) {
        int s = csr[idx];
        const float* xl_row = xl + (size_t)s * RS + w * C;
        float xlv[KC];
        float partial = 0.f;
        #pragma unroll
        for (int k = 0; k < KC; ++k) {
            xlv[k] = xl_row[l + 32 * k];
            float v = xlv[k] + xrv[k];
            v = (v > 0.f) ? v : 0.2f * v;      // leaky_relu(0.2)
            partial = fmaf(attv[k], v, partial);
        }
        #pragma unroll
        for (int off = 16; off > 0; off >>= 1)
            partial += __shfl_xor_sync(0xffffffffu, partial, off);
        float p = __expf(partial);
        denom += p;
        #pragma unroll
        for (int k = 0; k < KC; ++k)
            accv[k] = fmaf(p, xlv[k], accv[k]);
    }

    __shared__ float sh[H * C];
    float inv = 1.f / denom;
    #pragma unroll
    for (int k = 0; k < KC; ++k)
        sh[w * C + l + 32 * k] = accv[k] * inv;
    __syncthreads();

    if (threadIdx.x < C) {
        int c = threadIdx.x;
        float s = 0.f;
        #pragma unroll
        for (int h = 0; h < H; ++h) s += sh[h * C + c];
        s = s * (1.f / H) + bias[c];
        if (RELU) s = fmaxf(s, 0.f);
        if (ADD_RES) s += resid[(size_t)node * C + c];
        out[(size_t)node * C + c] = s;
    }
}

// ---------------------------------------------------------------------------
// Launch. Fused layer-1 GEMM at launch #4 (ncu's observed capture slot).
// ---------------------------------------------------------------------------
static inline int cdiv(int a, int b) { return (a + b - 1) / b; }

extern "C" void kernel_launch(void* const* d_in, const int* in_sizes, int n_in,
                              void* d_out, int out_size) {
    const float* x    = (const float*)d_in[0];
    const int*   ei   = (const int*)d_in[1];
    const float* Wl1  = (const float*)d_in[2];
    const float* Wr1  = (const float*)d_in[3];
    const float* att1 = (const float*)d_in[4];
    const float* b1   = (const float*)d_in[5];
    const float* Wl2  = (const float*)d_in[6];
    const float* Wr2  = (const float*)d_in[7];
    const float* att2 = (const float*)d_in[8];
    const float* b2   = (const float*)d_in[9];
    const float* Wlin = (const float*)d_in[10];
    const float* blin = (const float*)d_in[11];
    float* out = (float*)d_out;

    const int N = in_sizes[0] / F_IN;   // 50000
    const int E = in_sizes[1] / 2;      // 400000
    constexpr int N1 = 2 * HEADS * HID;    // 1024 fused layer-1 width
    constexpr int N2 = 2 * HEADS * N_CLS;  // 512 fused layer-2 width

    float *x1, *x2, *h1;
    __half *xh, *xlo, *h1h, *h1l, *w1h, *w1l, *w2h, *w2l, *wlih, *wlil;
    int *deg, *rowptr, *cursor, *csr;
    cudaGetSymbolAddress((void**)&x1,     g_x1);
    cudaGetSymbolAddress((void**)&x2,     g_x2);
    cudaGetSymbolAddress((void**)&h1,     g_h1);
    cudaGetSymbolAddress((void**)&xh,     g_xh);
    cudaGetSymbolAddress((void**)&xlo,    g_xlo);
    cudaGetSymbolAddress((void**)&h1h,    g_h1h);
    cudaGetSymbolAddress((void**)&h1l,    g_h1l);
    cudaGetSymbolAddress((void**)&w1h,    g_w1h);
    cudaGetSymbolAddress((void**)&w1l,    g_w1l);
    cudaGetSymbolAddress((void**)&w2h,    g_w2h);
    cudaGetSymbolAddress((void**)&w2l,    g_w2l);
    cudaGetSymbolAddress((void**)&wlih,   g_wlih);
    cudaGetSymbolAddress((void**)&wlil,   g_wlil);
    cudaGetSymbolAddress((void**)&deg,    g_deg);
    cudaGetSymbolAddress((void**)&rowptr, g_rowptr);
    cudaGetSymbolAddress((void**)&cursor, g_cursor);
    cudaGetSymbolAddress((void**)&csr,    g_csr);

    // ---- launches 1-3: pre-split layer-1 operands (Wl into rows 0..511,
    //      Wr into rows 512..1023 of the combined transposed planes) ----
    k_split_bt<<<cdiv(F_IN * HEADS * HID, 256), 256>>>(Wl1, w1h, w1l, F_IN, HEADS * HID);
    k_split_bt<<<cdiv(F_IN * HEADS * HID, 256), 256>>>(
        Wr1, w1h + (size_t)(HEADS * HID) * F_IN, w1l + (size_t)(HEADS * HID) * F_IN,
        F_IN, HEADS * HID);
    k_split_row<<<cdiv(N * F_IN, 256), 256>>>(x, xh, xlo, N * F_IN);

    // ---- launch 4: fused layer-1 GEMM (xl|xr in one shot; ncu slot) ----
    {
        dim3 g(cdiv(N1, 64), cdiv(N, 128));   // 16 x 391
        k_mma_h<<<g, 256>>>(xh, xlo, w1h, w1l, x1, N, N1, F_IN, nullptr);
    }

    // ---- residual GEMM into out ----
    k_split_bt<<<cdiv(F_IN * N_CLS, 256), 256>>>(Wlin, wlih, wlil, F_IN, N_CLS);
    {
        dim3 g(cdiv(N_CLS, 64), cdiv(N, 128));
        k_mma_h<<<g, 256>>>(xh, xlo, wlih, wlil, out, N, N_CLS, F_IN, blin);
    }

    // ---- dtype detect + CSR build ----
    k_flag_init<<<1, 1>>>();
    k_detect<<<cdiv(E, 256), 256>>>(ei, E);
    k_init_deg<<<cdiv(N, 256), 256>>>(deg, N);
    k_hist<<<cdiv(E, 256), 256>>>(ei, E, deg);
    k_scan<<<1, 1024>>>(deg, rowptr, N);
    k_cursor_self<<<cdiv(N, 256), 256>>>(rowptr, cursor, csr, N);
    k_scatter_edges<<<cdiv(E, 256), 256>>>(ei, E, cursor, csr);

    // ---- GAT layer 1 (fused, relu) -> h1 ----
    k_gatv2<HID, N1, true, false><<<N, 256>>>(
        x1, x1 + HEADS * HID, att1, b1, rowptr, csr, nullptr, h1);

    // ---- layer-2: split h1 + fused weights, one GEMM ----
    k_split_row<<<cdiv(N * HID, 256), 256>>>(h1, h1h, h1l, N * HID);
    k_split_bt<<<cdiv(HID * HEADS * N_CLS, 256), 256>>>(Wl2, w2h, w2l, HID, HEADS * N_CLS);
    k_split_bt<<<cdiv(HID * HEADS * N_CLS, 256), 256>>>(
        Wr2, w2h + (size_t)(HEADS * N_CLS) * HID, w2l + (size_t)(HEADS * N_CLS) * HID,
        HID, HEADS * N_CLS);
    {
        dim3 g(cdiv(N2, 64), cdiv(N, 128));   // 8 x 391
        k_mma_h<<<g, 256>>>(h1h, h1l, w2h, w2l, x2, N, N2, HID, nullptr);
    }

    // ---- GAT layer 2 (fused) + residual -> out ----
    k_gatv2<N_CLS, N2, false, true><<<N, 256>>>(
        x2, x2 + HEADS * N_CLS, att2, b2, rowptr, csr, out, out);
}